// round 3
// baseline (speedup 1.0000x reference)
#include <cuda_runtime.h>

// LinearActorNet: B=2048 samples, K=512 features, N=256 actions, T=64 tasks.
// task_id / action are INT32 on device (JAX x64-disabled canonicalization).
// out layout (float32): [action(B) | log_prob(B) | entropy(B)]
//
// Strategy: group samples by task (deterministic in-block compaction), then
// per (task, 16-row tile) block: smem xs tile, per-thread column GEMM
// (FMA-pipe bound), block-wide log-softmax reductions.

#define BB 2048
#define KK 512
#define NN 256
#define TT 64
#define TM 16
#define NTHREADS 256

__global__ __launch_bounds__(NTHREADS, 2)
void actor_kernel(const float* __restrict__ xs,
                  const int* __restrict__ task_id,
                  const int* __restrict__ action,
                  const float* __restrict__ W,
                  const float* __restrict__ bias,
                  float* __restrict__ out)
{
    __shared__ float xs_s[TM][KK];                 // 32 KB
    __shared__ unsigned short list[BB];            // 4 KB
    __shared__ int tcnt[NTHREADS];                 // 1 KB
    __shared__ float redm[TM][8];
    __shared__ float reda[TM][8];
    __shared__ float redb[TM][8];

    const int tid  = threadIdx.x;
    const int t    = blockIdx.x;
    const int lane = tid & 31;
    const int wid  = tid >> 5;

    // ---- deterministic compaction of sample indices with task_id == t ----
    // Every block of the same task builds the IDENTICAL ordered list, so
    // sibling tile-blocks partition samples disjointly.
    const int per  = BB / NTHREADS;                // 8 samples per thread
    const int base = tid * per;
    int cnt = 0;
    #pragma unroll
    for (int i = 0; i < per; i++)
        if (task_id[base + i] == t) cnt++;
    tcnt[tid] = cnt;
    __syncthreads();
    // Hillis-Steele inclusive scan over 256 counts
    for (int off = 1; off < NTHREADS; off <<= 1) {
        int v = tcnt[tid];
        int a = (tid >= off) ? tcnt[tid - off] : 0;
        __syncthreads();
        tcnt[tid] = v + a;
        __syncthreads();
    }
    const int total = tcnt[NTHREADS - 1];
    int pos = tcnt[tid] - cnt;
    #pragma unroll
    for (int i = 0; i < per; i++)
        if (task_id[base + i] == t) list[pos++] = (unsigned short)(base + i);
    __syncthreads();

    const float* __restrict__ Wt = W + (size_t)t * (KK * NN) + tid;  // column n = tid
    const float  bv = bias[t * NN + tid];

    for (int tile = blockIdx.y; tile * TM < total; tile += gridDim.y) {
        const int m0 = tile * TM;
        const int mc = min(TM, total - m0);
        __syncthreads();   // protect xs_s / red arrays across tile iterations

        // ---- stage xs tile [TM][KK] into smem (float4, coalesced) ----
        #pragma unroll
        for (int i = 0; i < (TM * KK / 4) / NTHREADS; i++) {   // 8 iters
            int idx = i * NTHREADS + tid;
            int m = idx >> 7;          // 128 float4 per row
            int c = idx & 127;
            float4 v = make_float4(0.f, 0.f, 0.f, 0.f);
            if (m < mc) {
                const float4* src = (const float4*)(xs + (size_t)list[m0 + m] * KK);
                v = src[c];
            }
            *(float4*)&xs_s[m][c * 4] = v;
        }
        __syncthreads();

        // ---- GEMM: acc[m] = sum_k xs[m][k] * W[t][k][n] ----
        float acc[TM];
        #pragma unroll
        for (int m = 0; m < TM; m++) acc[m] = 0.f;

        #pragma unroll 2
        for (int k = 0; k < KK; k += 4) {
            float w0 = Wt[(k + 0) * NN];
            float w1 = Wt[(k + 1) * NN];
            float w2 = Wt[(k + 2) * NN];
            float w3 = Wt[(k + 3) * NN];
            #pragma unroll
            for (int m = 0; m < TM; m++) {
                float4 x = *(const float4*)&xs_s[m][k];   // warp broadcast LDS.128
                float a = acc[m];
                a = fmaf(x.x, w0, a);
                a = fmaf(x.y, w1, a);
                a = fmaf(x.z, w2, a);
                a = fmaf(x.w, w3, a);
                acc[m] = a;
            }
        }

        #pragma unroll
        for (int m = 0; m < TM; m++) acc[m] += bv;

        // ---- block-wide max per row ----
        float mx[TM];
        #pragma unroll
        for (int m = 0; m < TM; m++) {
            float v = acc[m];
            #pragma unroll
            for (int o = 16; o > 0; o >>= 1)
                v = fmaxf(v, __shfl_xor_sync(0xffffffffu, v, o));
            if (lane == 0) redm[m][wid] = v;
        }
        __syncthreads();
        #pragma unroll
        for (int m = 0; m < TM; m++) {
            float v = redm[m][0];
            #pragma unroll
            for (int w = 1; w < 8; w++) v = fmaxf(v, redm[m][w]);
            mx[m] = v;
        }

        // ---- block-wide sums: s1 = sum(exp(d)), s2 = sum(exp(d)*d) ----
        #pragma unroll
        for (int m = 0; m < TM; m++) {
            float d = acc[m] - mx[m];
            float e = __expf(d);
            float a1 = e, a2 = e * d;
            #pragma unroll
            for (int o = 16; o > 0; o >>= 1) {
                a1 += __shfl_xor_sync(0xffffffffu, a1, o);
                a2 += __shfl_xor_sync(0xffffffffu, a2, o);
            }
            if (lane == 0) { reda[m][wid] = a1; redb[m][wid] = a2; }
        }
        __syncthreads();

        // ---- outputs ----
        for (int m = 0; m < mc; m++) {
            float s1 = reda[m][0], s2 = redb[m][0];
            #pragma unroll
            for (int w = 1; w < 8; w++) { s1 += reda[m][w]; s2 += redb[m][w]; }
            const int   gb   = list[m0 + m];
            const int   a    = action[gb];
            const float logS = logf(s1);
            if (tid == a)
                out[BB + gb] = acc[m] - mx[m] - logS;       // log_prob
            if (tid == 0) {
                out[gb]          = (float)a;                // action (as float)
                out[2 * BB + gb] = logS - s2 / s1;          // entropy
            }
        }
    }
}

extern "C" void kernel_launch(void* const* d_in, const int* in_sizes, int n_in,
                              void* d_out, int out_size) {
    const float* xs      = (const float*)d_in[0];
    const int*   task_id = (const int*)d_in[1];
    const int*   action  = (const int*)d_in[2];
    const float* W       = (const float*)d_in[3];
    const float* bias    = (const float*)d_in[4];
    float*       out     = (float*)d_out;

    dim3 grid(TT, 4);
    actor_kernel<<<grid, NTHREADS>>>(xs, task_id, action, W, bias, out);
}

// round 4
// speedup vs baseline: 1.3420x; 1.3420x over previous
#include <cuda_runtime.h>

// LinearActorNet: B=2048, K=512, N=256, T=64. task_id/action int32.
// out layout (float32): [action(B) | log_prob(B) | entropy(B)]
//
// Grouped-by-task tile GEMM with packed f32x2 FFMA (Blackwell FFMA2):
//  - 128 threads/CTA, each thread owns 2 output columns (n=tid, n=tid+128)
//  - 16-row xs tile in smem, broadcast LDS.128, even/odd-k packed accumulators
//  - block-wide log-softmax reductions (4 warps)

#define BB 2048
#define KK 512
#define NN 256
#define TT 64
#define TM 16
#define NT 128

union f2u { float2 f; unsigned long long u; };

__device__ __forceinline__ unsigned long long pk(float lo, float hi) {
    f2u u; u.f = make_float2(lo, hi); return u.u;
}
__device__ __forceinline__ float fold(unsigned long long v) {
    f2u u; u.u = v; return u.f.x + u.f.y;
}

#define FFMA2(d, a, b) \
    asm("fma.rn.f32x2 %0, %1, %2, %0;" : "+l"(d) : "l"(a), "l"(b))

__global__ __launch_bounds__(NT, 4)
void actor_kernel(const float* __restrict__ xs,
                  const int* __restrict__ task_id,
                  const int* __restrict__ action,
                  const float* __restrict__ W,
                  const float* __restrict__ bias,
                  float* __restrict__ out)
{
    __shared__ float xs_s[TM][KK];          // 32 KB
    __shared__ unsigned short list[BB];     // 4 KB
    __shared__ int tcnt[NT];
    __shared__ float redm[TM][4];
    __shared__ float reda[TM][4];
    __shared__ float redb[TM][4];

    const int tid  = threadIdx.x;
    const int t    = blockIdx.x;
    const int lane = tid & 31;
    const int wid  = tid >> 5;

    // ---- deterministic compaction of sample indices with task_id == t ----
    const int per  = BB / NT;               // 16 per thread
    const int base = tid * per;
    int cnt = 0;
    #pragma unroll
    for (int i = 0; i < per; i++)
        if (task_id[base + i] == t) cnt++;
    tcnt[tid] = cnt;
    __syncthreads();
    for (int off = 1; off < NT; off <<= 1) {     // Hillis-Steele scan
        int v = tcnt[tid];
        int a = (tid >= off) ? tcnt[tid - off] : 0;
        __syncthreads();
        tcnt[tid] = v + a;
        __syncthreads();
    }
    const int total = tcnt[NT - 1];
    int pos = tcnt[tid] - cnt;
    #pragma unroll
    for (int i = 0; i < per; i++)
        if (task_id[base + i] == t) list[pos++] = (unsigned short)(base + i);
    __syncthreads();

    const float* __restrict__ Wt = W + (size_t)t * (KK * NN) + tid;
    const float bv0 = bias[t * NN + tid];
    const float bv1 = bias[t * NN + tid + 128];

    for (int tile = blockIdx.y; tile * TM < total; tile += gridDim.y) {
        const int m0 = tile * TM;
        const int mc = min(TM, total - m0);
        __syncthreads();

        // ---- stage xs tile [TM][KK] into smem (float4, coalesced) ----
        #pragma unroll
        for (int i = 0; i < (TM * KK / 4) / NT; i++) {   // 16 iters
            int idx = i * NT + tid;
            int m = idx >> 7;
            int c = idx & 127;
            float4 v = make_float4(0.f, 0.f, 0.f, 0.f);
            if (m < mc) {
                const float4* src = (const float4*)(xs + (size_t)list[m0 + m] * KK);
                v = src[c];
            }
            *(float4*)&xs_s[m][c * 4] = v;
        }
        __syncthreads();

        // ---- GEMM: packed f32x2 partial accumulators (even/odd k-slot) ----
        unsigned long long acc0[TM], acc1[TM];
        #pragma unroll
        for (int m = 0; m < TM; m++) { acc0[m] = 0ull; acc1[m] = 0ull; }

        #pragma unroll 2
        for (int k = 0; k < KK; k += 4) {
            const float* wk = Wt + k * NN;
            float a00 = wk[0],        a01 = wk[NN],       a02 = wk[2*NN],       a03 = wk[3*NN];
            float b00 = wk[128],      b01 = wk[NN+128],   b02 = wk[2*NN+128],   b03 = wk[3*NN+128];
            unsigned long long wA0 = pk(a00, a01), wA1 = pk(a02, a03);
            unsigned long long wB0 = pk(b00, b01), wB1 = pk(b02, b03);
            #pragma unroll
            for (int m = 0; m < TM; m++) {
                ulonglong2 xv = *(const ulonglong2*)&xs_s[m][k];  // LDS.128 broadcast
                FFMA2(acc0[m], xv.x, wA0);
                FFMA2(acc0[m], xv.y, wA1);
                FFMA2(acc1[m], xv.x, wB0);
                FFMA2(acc1[m], xv.y, wB1);
            }
        }

        float v0[TM], v1[TM];
        #pragma unroll
        for (int m = 0; m < TM; m++) {
            v0[m] = fold(acc0[m]) + bv0;
            v1[m] = fold(acc1[m]) + bv1;
        }

        // ---- block-wide max per row ----
        float mx[TM];
        #pragma unroll
        for (int m = 0; m < TM; m++) {
            float v = fmaxf(v0[m], v1[m]);
            #pragma unroll
            for (int o = 16; o > 0; o >>= 1)
                v = fmaxf(v, __shfl_xor_sync(0xffffffffu, v, o));
            if (lane == 0) redm[m][wid] = v;
        }
        __syncthreads();
        #pragma unroll
        for (int m = 0; m < TM; m++)
            mx[m] = fmaxf(fmaxf(redm[m][0], redm[m][1]),
                          fmaxf(redm[m][2], redm[m][3]));

        // ---- block-wide sums: s1 = sum(exp(d)), s2 = sum(exp(d)*d) ----
        #pragma unroll
        for (int m = 0; m < TM; m++) {
            float d0 = v0[m] - mx[m];
            float d1 = v1[m] - mx[m];
            float e0 = __expf(d0), e1 = __expf(d1);
            float s1 = e0 + e1;
            float s2 = e0 * d0 + e1 * d1;
            #pragma unroll
            for (int o = 16; o > 0; o >>= 1) {
                s1 += __shfl_xor_sync(0xffffffffu, s1, o);
                s2 += __shfl_xor_sync(0xffffffffu, s2, o);
            }
            if (lane == 0) { reda[m][wid] = s1; redb[m][wid] = s2; }
        }
        __syncthreads();

        // ---- outputs ----
        #pragma unroll
        for (int m = 0; m < TM; m++) {
            if (m >= mc) break;
            float s1 = reda[m][0] + reda[m][1] + reda[m][2] + reda[m][3];
            float s2 = redb[m][0] + redb[m][1] + redb[m][2] + redb[m][3];
            const int   gb   = list[m0 + m];
            const int   a    = action[gb];
            const float logS = logf(s1);
            if (tid == (a & 127)) {
                float chosen = (a < 128) ? v0[m] : v1[m];
                out[BB + gb] = chosen - mx[m] - logS;       // log_prob
            }
            if (tid == 0) {
                out[gb]          = (float)a;                // action (as float)
                out[2 * BB + gb] = logS - s2 / s1;          // entropy
            }
        }
    }
}

extern "C" void kernel_launch(void* const* d_in, const int* in_sizes, int n_in,
                              void* d_out, int out_size) {
    const float* xs      = (const float*)d_in[0];
    const int*   task_id = (const int*)d_in[1];
    const int*   action  = (const int*)d_in[2];
    const float* W       = (const float*)d_in[3];
    const float* bias    = (const float*)d_in[4];
    float*       out     = (float*)d_out;

    dim3 grid(TT, 4);
    actor_kernel<<<grid, NT>>>(xs, task_id, action, W, bias, out);
}